// round 6
// baseline (speedup 1.0000x reference)
#include <cuda_runtime.h>
#include <cuda_bf16.h>
#include <math.h>
#include <stdint.h>

#define BB 64
#define LL 900
#define DD 64
#define MT 128
#define NT 64
#define NKT 15
#define SC 0.180336893f   // 0.125 * log2(e)

#define STR  72           // bf16 elems per smem row (144B)
#define STRB 144

// smem byte offsets
#define SQHI 0
#define SQLO 18432
#define SKHI 36864
#define SKLO 46080
#define SVHI 55296
#define SVLO 64512
#define SPHI 73728
#define SPLO 92160
#define SSL   110592
#define SSINV 111104
#define SMEM_BYTES 111616

#define NELEM (BB * LL * DD)

// preconverted hi/lo bf16 tensors
__device__ __nv_bfloat16 g_qhi[NELEM], g_qlo[NELEM];
__device__ __nv_bfloat16 g_khi[NELEM], g_klo[NELEM];
__device__ __nv_bfloat16 g_vhi[NELEM], g_vlo[NELEM];

static __device__ __forceinline__ uint32_t smem_u32(const void* p) {
    uint32_t a;
    asm("{ .reg .u64 t; cvta.to.shared.u64 t, %1; cvt.u32.u64 %0, t; }" : "=r"(a) : "l"(p));
    return a;
}
static __device__ __forceinline__ float ex2f(float x) {
    float r; asm("ex2.approx.ftz.f32 %0, %1;" : "=f"(r) : "f"(x)); return r;
}
// pack two f32 -> bf16x2 {hi=cvt(h), lo=cvt(lo_arg)}
static __device__ __forceinline__ uint32_t cvt2(float hi, float lo) {
    uint32_t r; asm("cvt.rn.bf16x2.f32 %0, %1, %2;" : "=r"(r) : "f"(hi), "f"(lo)); return r;
}
static __device__ __forceinline__ void cpa16(uint32_t dst, const void* src, int sz) {
    asm volatile("cp.async.cg.shared.global [%0], [%1], 16, %2;"
                 :: "r"(dst), "l"(src), "r"(sz) : "memory");
}
#define CP_COMMIT() asm volatile("cp.async.commit_group;" ::: "memory")
#define CP_WAIT0()  asm volatile("cp.async.wait_group 0;" ::: "memory")

#define LDM4(r, a) \
    asm volatile("ldmatrix.sync.aligned.m8n8.x4.shared.b16 {%0,%1,%2,%3}, [%4];" \
        : "=r"((r)[0]), "=r"((r)[1]), "=r"((r)[2]), "=r"((r)[3]) : "r"(a))
#define LDM4T(r, a) \
    asm volatile("ldmatrix.sync.aligned.m8n8.x4.trans.shared.b16 {%0,%1,%2,%3}, [%4];" \
        : "=r"((r)[0]), "=r"((r)[1]), "=r"((r)[2]), "=r"((r)[3]) : "r"(a))
#define MMA(d, a, b0, b1) \
    asm volatile("mma.sync.aligned.m16n8k16.row.col.f32.bf16.bf16.f32 " \
        "{%0,%1,%2,%3}, {%4,%5,%6,%7}, {%8,%9}, {%0,%1,%2,%3};" \
        : "+f"((d)[0]), "+f"((d)[1]), "+f"((d)[2]), "+f"((d)[3]) \
        : "r"((a)[0]), "r"((a)[1]), "r"((a)[2]), "r"((a)[3]), "r"(b0), "r"(b1))

// ---------- precvt: f32 -> (hi, lo) bf16 pairs for q,k,v ----------
__global__ __launch_bounds__(256)
void precvt(const float* __restrict__ q, const float* __restrict__ k,
            const float* __restrict__ v)
{
    const int N4 = NELEM / 4;
    int i = blockIdx.x * blockDim.x + threadIdx.x;
    if (i >= 3 * N4) return;
    int t  = i / N4;
    int i4 = i - t * N4;
    const float4* src = (const float4*)(t == 0 ? q : (t == 1 ? k : v));
    __nv_bfloat16* hi = t == 0 ? g_qhi : (t == 1 ? g_khi : g_vhi);
    __nv_bfloat16* lo = t == 0 ? g_qlo : (t == 1 ? g_klo : g_vlo);
    float4 val = src[i4];
    uint32_t h01 = cvt2(val.y, val.x);
    uint32_t h23 = cvt2(val.w, val.z);
    float h0 = __uint_as_float(h01 << 16);
    float h1 = __uint_as_float(h01 & 0xFFFF0000u);
    float h2 = __uint_as_float(h23 << 16);
    float h3 = __uint_as_float(h23 & 0xFFFF0000u);
    uint32_t l01 = cvt2(val.y - h1, val.x - h0);
    uint32_t l23 = cvt2(val.w - h3, val.z - h2);
    ((uint2*)hi)[i4] = make_uint2(h01, h23);
    ((uint2*)lo)[i4] = make_uint2(l01, l23);
}

// ---------- fused attention ----------
__global__ void __launch_bounds__(256, 2)
attn_mma(const int* __restrict__ dur, float* __restrict__ out, float* __restrict__ score)
{
    extern __shared__ char s[];
    const uint32_t sb = smem_u32(s);

    const int tid = threadIdx.x;
    const int l   = tid & 31;
    const int wid = tid >> 5;
    const int mi  = wid >> 1;
    const int ni  = wid & 1;
    const int b   = blockIdx.y;
    const int q0  = blockIdx.x * MT;
    const int durb = dur[b];
    const size_t bi = (size_t)b * LL * DD;

    float* Sb = score + (size_t)b * LL * LL;

    if (tid < 128) *(float*)(s + SSL + tid * 4) = 0.f;

    // ---- prologue: cp.async Q (hi/lo) + K0/V0 ----
    #pragma unroll
    for (int w = 0; w < 8; w++) {
        int c = tid + 256 * w;          // 0..2047
        int buf = c >> 10;              // 0:hi 1:lo
        int r = (c >> 3) & 127;
        int ch = c & 7;
        int rg = q0 + r;
        int rc = rg < LL ? rg : LL - 1;
        const __nv_bfloat16* src = (buf ? g_qlo : g_qhi) + bi + (size_t)rc * DD + ch * 8;
        cpa16(sb + (buf ? SQLO : SQHI) + r * STRB + ch * 16, src, rg < LL ? 16 : 0);
    }
    {   // K0 + V0
        #pragma unroll
        for (int w = 0; w < 8; w++) {
            int c = tid + 256 * w;
            int buf = c >> 9;           // 0..3
            int r = (c >> 3) & 63;
            int ch = c & 7;
            int rg = r;                 // c0t = 0
            const __nv_bfloat16* base = buf == 0 ? g_khi : buf == 1 ? g_klo
                                      : buf == 2 ? g_vhi : g_vlo;
            uint32_t off = buf == 0 ? SKHI : buf == 1 ? SKLO : buf == 2 ? SVHI : SVLO;
            cpa16(sb + off + r * STRB + ch * 16, base + bi + (size_t)rg * DD + ch * 8, 16);
        }
    }
    CP_COMMIT();

    float oacc[2][4][4];
    #pragma unroll
    for (int a = 0; a < 2; a++)
        #pragma unroll
        for (int nb = 0; nb < 4; nb++)
            #pragma unroll
            for (int j = 0; j < 4; j++) oacc[a][nb][j] = 0.f;
    float rs[2][2] = {{0.f, 0.f}, {0.f, 0.f}};

    const uint32_t aSel = (l & 16) ? 16u : 0u;
    const uint32_t bRow = (l & 7) + ((l & 16) ? 8 : 0);
    const uint32_t bSel = (l & 8) ? 16u : 0u;
    const uint32_t aRow = (l & 15);

    for (int kt = 0; kt < NKT; kt++) {
        const int c0t = kt * NT;
        CP_WAIT0();
        __syncthreads();        // K/V/Q tiles ready; prev GEMM2 done (P/V free)

        // ---- GEMM1: S = Q K^T (3-term split) ----
        float sacc[2][4][4];
        #pragma unroll
        for (int a = 0; a < 2; a++)
            #pragma unroll
            for (int nb = 0; nb < 4; nb++)
                #pragma unroll
                for (int j = 0; j < 4; j++) sacc[a][nb][j] = 0.f;

        #pragma unroll
        for (int ks = 0; ks < 4; ks++) {
            const uint32_t kb = ks * 32;
            uint32_t ahi[2][4], alo[2][4], bhi[2][4], blo[2][4];
            #pragma unroll
            for (int a = 0; a < 2; a++) {
                uint32_t ro = (mi * 32 + a * 16 + aRow) * STRB + kb + aSel;
                LDM4(ahi[a], sb + SQHI + ro);
                LDM4(alo[a], sb + SQLO + ro);
            }
            #pragma unroll
            for (int np = 0; np < 2; np++) {
                uint32_t ro = (ni * 32 + np * 16 + bRow) * STRB + kb + bSel;
                LDM4(bhi[np], sb + SKHI + ro);
                LDM4(blo[np], sb + SKLO + ro);
            }
            #pragma unroll
            for (int a = 0; a < 2; a++)
                #pragma unroll
                for (int np = 0; np < 2; np++) {
                    MMA(sacc[a][2*np],   ahi[a], bhi[np][0], bhi[np][1]);
                    MMA(sacc[a][2*np],   alo[a], bhi[np][0], bhi[np][1]);
                    MMA(sacc[a][2*np],   ahi[a], blo[np][0], blo[np][1]);
                    MMA(sacc[a][2*np+1], ahi[a], bhi[np][2], bhi[np][3]);
                    MMA(sacc[a][2*np+1], alo[a], bhi[np][2], bhi[np][3]);
                    MMA(sacc[a][2*np+1], ahi[a], blo[np][2], blo[np][3]);
                }
        }

        // ---- epilogue: p = exp(mask(S*scale)); P->smem hi/lo, p->score (unnormalized) ----
        #pragma unroll
        for (int a = 0; a < 2; a++) {
            const int R0  = mi * 32 + a * 16 + (l >> 2);
            const int r0g = q0 + R0, r1g = r0g + 8;
            #pragma unroll
            for (int nb = 0; nb < 4; nb++) {
                const int col = ni * 32 + nb * 8 + 2 * (l & 3);
                const int cg  = c0t + col;
                float t0 = sacc[a][nb][0] * SC, t1 = sacc[a][nb][1] * SC;
                float t2 = sacc[a][nb][2] * SC, t3 = sacc[a][nb][3] * SC;
                if (r0g >= durb || cg     >= durb) t0 = 0.f;
                if (r0g >= durb || cg + 1 >= durb) t1 = 0.f;
                if (r1g >= durb || cg     >= durb) t2 = 0.f;
                if (r1g >= durb || cg + 1 >= durb) t3 = 0.f;
                float p0 = ex2f(t0), p1 = ex2f(t1), p2 = ex2f(t2), p3 = ex2f(t3);
                if (cg >= LL) { p0 = 0.f; p1 = 0.f; p2 = 0.f; p3 = 0.f; }
                rs[a][0] += p0 + p1;
                rs[a][1] += p2 + p3;
                uint32_t h01 = cvt2(p1, p0);
                uint32_t h23 = cvt2(p3, p2);
                float l0 = p0 - __uint_as_float(h01 << 16);
                float l1 = p1 - __uint_as_float(h01 & 0xFFFF0000u);
                float l2 = p2 - __uint_as_float(h23 << 16);
                float l3 = p3 - __uint_as_float(h23 & 0xFFFF0000u);
                uint32_t o0 = (R0 * STR + col) * 2;
                uint32_t o1 = ((R0 + 8) * STR + col) * 2;
                *(uint32_t*)(s + SPHI + o0) = h01;
                *(uint32_t*)(s + SPLO + o0) = cvt2(l1, l0);
                *(uint32_t*)(s + SPHI + o1) = h23;
                *(uint32_t*)(s + SPLO + o1) = cvt2(l3, l2);
                if (cg < LL) {
                    if (r0g < LL) *(float2*)(Sb + (size_t)r0g * LL + cg) = make_float2(p0, p1);
                    if (r1g < LL) *(float2*)(Sb + (size_t)r1g * LL + cg) = make_float2(p2, p3);
                }
            }
        }
        __syncthreads();        // P ready; all warps past GEMM1 -> K buffers free

        // ---- prefetch K(kt+1) (overlaps GEMM2) ----
        if (kt + 1 < NKT) {
            const int c0n = c0t + NT;
            #pragma unroll
            for (int w = 0; w < 4; w++) {
                int c = tid + 256 * w;      // 0..1023
                int buf = c >> 9;           // 0:hi 1:lo
                int r = (c >> 3) & 63;
                int ch = c & 7;
                int rg = c0n + r;
                int rc = rg < LL ? rg : LL - 1;
                const __nv_bfloat16* src = (buf ? g_klo : g_khi) + bi + (size_t)rc * DD + ch * 8;
                cpa16(sb + (buf ? SKLO : SKHI) + r * STRB + ch * 16, src, rg < LL ? 16 : 0);
            }
        }

        // ---- GEMM2: out += P V ----
        #pragma unroll
        for (int ks = 0; ks < 4; ks++) {
            const uint32_t kb = ks * 32;
            uint32_t ahi[2][4], alo[2][4], bhi[2][4], blo[2][4];
            #pragma unroll
            for (int a = 0; a < 2; a++) {
                uint32_t ro = (mi * 32 + a * 16 + aRow) * STRB + kb + aSel;
                LDM4(ahi[a], sb + SPHI + ro);
                LDM4(alo[a], sb + SPLO + ro);
            }
            #pragma unroll
            for (int np = 0; np < 2; np++) {
                uint32_t ro = (ks * 16 + aRow) * STRB + (ni * 32 + np * 16) * 2 + aSel;
                LDM4T(bhi[np], sb + SVHI + ro);
                LDM4T(blo[np], sb + SVLO + ro);
            }
            #pragma unroll
            for (int a = 0; a < 2; a++)
                #pragma unroll
                for (int np = 0; np < 2; np++) {
                    MMA(oacc[a][2*np],   ahi[a], bhi[np][0], bhi[np][1]);
                    MMA(oacc[a][2*np],   alo[a], bhi[np][0], bhi[np][1]);
                    MMA(oacc[a][2*np],   ahi[a], blo[np][0], blo[np][1]);
                    MMA(oacc[a][2*np+1], ahi[a], bhi[np][2], bhi[np][3]);
                    MMA(oacc[a][2*np+1], alo[a], bhi[np][2], bhi[np][3]);
                    MMA(oacc[a][2*np+1], ahi[a], blo[np][2], blo[np][3]);
                }
        }
        __syncthreads();        // all warps past GEMM2 -> V/P free

        // ---- prefetch V(kt+1), commit the K+V group ----
        if (kt + 1 < NKT) {
            const int c0n = c0t + NT;
            #pragma unroll
            for (int w = 0; w < 4; w++) {
                int c = tid + 256 * w;
                int buf = c >> 9;
                int r = (c >> 3) & 63;
                int ch = c & 7;
                int rg = c0n + r;
                int rc = rg < LL ? rg : LL - 1;
                const __nv_bfloat16* src = (buf ? g_vlo : g_vhi) + bi + (size_t)rc * DD + ch * 8;
                cpa16(sb + (buf ? SVLO : SVHI) + r * STRB + ch * 16, src, rg < LL ? 16 : 0);
            }
            CP_COMMIT();
        }
    }

    // ---- rowsum reduce -> invl ----
    #pragma unroll
    for (int a = 0; a < 2; a++)
        #pragma unroll
        for (int h = 0; h < 2; h++) {
            float vsum = rs[a][h];
            vsum += __shfl_xor_sync(0xffffffffu, vsum, 1);
            vsum += __shfl_xor_sync(0xffffffffu, vsum, 2);
            if ((l & 3) == 0)
                atomicAdd((float*)(s + SSL) + (mi * 32 + a * 16 + (l >> 2) + 8 * h), vsum);
        }
    __syncthreads();
    if (tid < 128)
        ((float*)(s + SSINV))[tid] = 1.f / ((float*)(s + SSL))[tid];
    __syncthreads();

    const float* sinv = (const float*)(s + SSINV);

    // ---- out = (P V) * invl ----
    #pragma unroll
    for (int a = 0; a < 2; a++) {
        const int R0 = mi * 32 + a * 16 + (l >> 2);
        const float inv0 = sinv[R0], inv1 = sinv[R0 + 8];
        const int r0g = q0 + R0, r1g = r0g + 8;
        #pragma unroll
        for (int nb = 0; nb < 4; nb++) {
            const int d0 = ni * 32 + nb * 8 + 2 * (l & 3);
            if (r0g < LL)
                *(float2*)(out + ((size_t)b * LL + r0g) * DD + d0) =
                    make_float2(oacc[a][nb][0] * inv0, oacc[a][nb][1] * inv0);
            if (r1g < LL)
                *(float2*)(out + ((size_t)b * LL + r1g) * DD + d0) =
                    make_float2(oacc[a][nb][2] * inv1, oacc[a][nb][3] * inv1);
        }
    }

    // ---- fused score normalization: rescale exactly the float2s this thread wrote ----
    #pragma unroll
    for (int a = 0; a < 2; a++) {
        const int R0 = mi * 32 + a * 16 + (l >> 2);
        const float inv0 = sinv[R0], inv1 = sinv[R0 + 8];
        const int r0g = q0 + R0, r1g = r0g + 8;
        for (int kt = 0; kt < NKT; kt++) {
            const int c0t = kt * NT;
            #pragma unroll
            for (int nb = 0; nb < 4; nb++) {
                const int cg = c0t + ni * 32 + nb * 8 + 2 * (l & 3);
                if (cg < LL) {
                    if (r0g < LL) {
                        float2* p = (float2*)(Sb + (size_t)r0g * LL + cg);
                        float2 x = *p; x.x *= inv0; x.y *= inv0; *p = x;
                    }
                    if (r1g < LL) {
                        float2* p = (float2*)(Sb + (size_t)r1g * LL + cg);
                        float2 x = *p; x.x *= inv1; x.y *= inv1; *p = x;
                    }
                }
            }
        }
    }
}

extern "C" void kernel_launch(void* const* d_in, const int* in_sizes, int n_in,
                              void* d_out, int out_size)
{
    const float* q   = (const float*)d_in[0];
    const float* k   = (const float*)d_in[1];
    const float* v   = (const float*)d_in[2];
    const int*   dur = (const int*)d_in[3];

    float* out   = (float*)d_out;
    float* score = out + (size_t)BB * LL * DD;

    const int N4 = NELEM / 4;
    precvt<<<(3 * N4 + 255) / 256, 256>>>(q, k, v);

    cudaFuncSetAttribute(attn_mma, cudaFuncAttributeMaxDynamicSharedMemorySize, SMEM_BYTES);
    dim3 grd(8, BB);
    attn_mma<<<grd, 256, SMEM_BYTES>>>(dur, out, score);
}

// round 9
// speedup vs baseline: 1.8138x; 1.8138x over previous
#include <cuda_runtime.h>
#include <cuda_bf16.h>
#include <cuda_fp16.h>
#include <math.h>
#include <stdint.h>

#define BB 64
#define LL 900
#define DD 64
#define MT 128
#define NT 64
#define NKT 15
#define SC 0.180336893f   // 0.125 * log2(e)

#define STR  72           // 16-bit elems per smem row (144B)
#define STRB 144

// smem byte offsets
#define SQHI 0
#define SQLO 18432
#define SKHI 36864
#define SKLO 46080
#define SVHI 55296
#define SVLO 64512
#define SPHI 73728        // P: fp16 single (2-term GEMM2)
#define SSL   92160
#define SSINV 92672
#define SMEM_BYTES 93184

#define NELEM (BB * LL * DD)

__device__ __nv_bfloat16 g_qhi[NELEM], g_qlo[NELEM];
__device__ __nv_bfloat16 g_khi[NELEM], g_klo[NELEM];
__device__ __half        g_vhi[NELEM], g_vlo[NELEM];   // fp16 split for GEMM2
__device__ float g_invl[BB * LL];

static __device__ __forceinline__ uint32_t smem_u32(const void* p) {
    uint32_t a;
    asm("{ .reg .u64 t; cvta.to.shared.u64 t, %1; cvt.u32.u64 %0, t; }" : "=r"(a) : "l"(p));
    return a;
}
static __device__ __forceinline__ float ex2f(float x) {
    float r; asm("ex2.approx.ftz.f32 %0, %1;" : "=f"(r) : "f"(x)); return r;
}
// pack two f32 -> bf16x2
static __device__ __forceinline__ uint32_t cvt2(float hi, float lo) {
    uint32_t r; asm("cvt.rn.bf16x2.f32 %0, %1, %2;" : "=r"(r) : "f"(hi), "f"(lo)); return r;
}
// pack two f32 -> f16x2
static __device__ __forceinline__ uint32_t cvt2h(float hi, float lo) {
    uint32_t r; asm("cvt.rn.f16x2.f32 %0, %1, %2;" : "=r"(r) : "f"(hi), "f"(lo)); return r;
}
static __device__ __forceinline__ void cpa16(uint32_t dst, const void* src, int sz) {
    asm volatile("cp.async.cg.shared.global [%0], [%1], 16, %2;"
                 :: "r"(dst), "l"(src), "r"(sz) : "memory");
}
#define CP_COMMIT() asm volatile("cp.async.commit_group;" ::: "memory")
#define CP_WAIT0()  asm volatile("cp.async.wait_group 0;" ::: "memory")

#define LDM4(r, a) \
    asm volatile("ldmatrix.sync.aligned.m8n8.x4.shared.b16 {%0,%1,%2,%3}, [%4];" \
        : "=r"((r)[0]), "=r"((r)[1]), "=r"((r)[2]), "=r"((r)[3]) : "r"(a))
#define LDM4T(r, a) \
    asm volatile("ldmatrix.sync.aligned.m8n8.x4.trans.shared.b16 {%0,%1,%2,%3}, [%4];" \
        : "=r"((r)[0]), "=r"((r)[1]), "=r"((r)[2]), "=r"((r)[3]) : "r"(a))
#define MMA(d, a, b0, b1) \
    asm volatile("mma.sync.aligned.m16n8k16.row.col.f32.bf16.bf16.f32 " \
        "{%0,%1,%2,%3}, {%4,%5,%6,%7}, {%8,%9}, {%0,%1,%2,%3};" \
        : "+f"((d)[0]), "+f"((d)[1]), "+f"((d)[2]), "+f"((d)[3]) \
        : "r"((a)[0]), "r"((a)[1]), "r"((a)[2]), "r"((a)[3]), "r"(b0), "r"(b1))
#define MMAH(d, a, b0, b1) \
    asm volatile("mma.sync.aligned.m16n8k16.row.col.f32.f16.f16.f32 " \
        "{%0,%1,%2,%3}, {%4,%5,%6,%7}, {%8,%9}, {%0,%1,%2,%3};" \
        : "+f"((d)[0]), "+f"((d)[1]), "+f"((d)[2]), "+f"((d)[3]) \
        : "r"((a)[0]), "r"((a)[1]), "r"((a)[2]), "r"((a)[3]), "r"(b0), "r"(b1))

// ---------- precvt: q,k -> bf16 hi/lo;  v -> fp16 hi/lo ----------
__global__ __launch_bounds__(256)
void precvt(const float* __restrict__ q, const float* __restrict__ k,
            const float* __restrict__ v)
{
    const int N4 = NELEM / 4;
    int i = blockIdx.x * blockDim.x + threadIdx.x;
    if (i >= 3 * N4) return;
    int t  = i / N4;
    int i4 = i - t * N4;
    if (t < 2) {
        const float4* src = (const float4*)(t == 0 ? q : k);
        __nv_bfloat16* hi = t == 0 ? g_qhi : g_khi;
        __nv_bfloat16* lo = t == 0 ? g_qlo : g_klo;
        float4 val = src[i4];
        uint32_t h01 = cvt2(val.y, val.x);
        uint32_t h23 = cvt2(val.w, val.z);
        float h0 = __uint_as_float(h01 << 16);
        float h1 = __uint_as_float(h01 & 0xFFFF0000u);
        float h2 = __uint_as_float(h23 << 16);
        float h3 = __uint_as_float(h23 & 0xFFFF0000u);
        uint32_t l01 = cvt2(val.y - h1, val.x - h0);
        uint32_t l23 = cvt2(val.w - h3, val.z - h2);
        ((uint2*)hi)[i4] = make_uint2(h01, h23);
        ((uint2*)lo)[i4] = make_uint2(l01, l23);
    } else {
        float4 val = ((const float4*)v)[i4];
        __half h0 = __float2half(val.x), h1 = __float2half(val.y);
        __half h2 = __float2half(val.z), h3 = __float2half(val.w);
        __half l0 = __float2half(val.x - __half2float(h0));
        __half l1 = __float2half(val.y - __half2float(h1));
        __half l2 = __float2half(val.z - __half2float(h2));
        __half l3 = __float2half(val.w - __half2float(h3));
        __half2 hv0 = __halves2half2(h0, h1), hv1 = __halves2half2(h2, h3);
        __half2 lv0 = __halves2half2(l0, l1), lv1 = __halves2half2(l2, l3);
        ((uint2*)g_vhi)[i4] = make_uint2(*(uint32_t*)&hv0, *(uint32_t*)&hv1);
        ((uint2*)g_vlo)[i4] = make_uint2(*(uint32_t*)&lv0, *(uint32_t*)&lv1);
    }
}

// ---------- fused attention ----------
__global__ void __launch_bounds__(256, 2)
attn_mma(const int* __restrict__ dur, float* __restrict__ out, float* __restrict__ score)
{
    extern __shared__ char s[];
    const uint32_t sb = smem_u32(s);

    const int tid = threadIdx.x;
    const int l   = tid & 31;
    const int wid = tid >> 5;
    const int mi  = wid >> 1;
    const int ni  = wid & 1;
    const int b   = blockIdx.y;
    const int q0  = blockIdx.x * MT;
    const int durb = dur[b];
    const size_t bi = (size_t)b * LL * DD;

    float* Sb = score + (size_t)b * LL * LL;

    if (tid < 128) *(float*)(s + SSL + tid * 4) = 0.f;

    // ---- prologue: cp.async Q (hi/lo) + K0/V0 ----
    #pragma unroll
    for (int w = 0; w < 8; w++) {
        int c = tid + 256 * w;          // 0..2047
        int buf = c >> 10;              // 0:hi 1:lo
        int r = (c >> 3) & 127;
        int ch = c & 7;
        int rg = q0 + r;
        int rc = rg < LL ? rg : LL - 1;
        const __nv_bfloat16* src = (buf ? g_qlo : g_qhi) + bi + (size_t)rc * DD + ch * 8;
        cpa16(sb + (buf ? SQLO : SQHI) + r * STRB + ch * 16, src, rg < LL ? 16 : 0);
    }
    {   // K0 + V0
        #pragma unroll
        for (int w = 0; w < 8; w++) {
            int c = tid + 256 * w;
            int buf = c >> 9;           // 0..3
            int r = (c >> 3) & 63;
            int ch = c & 7;
            const void* base = buf == 0 ? (const void*)g_khi : buf == 1 ? (const void*)g_klo
                             : buf == 2 ? (const void*)g_vhi : (const void*)g_vlo;
            uint32_t off = buf == 0 ? SKHI : buf == 1 ? SKLO : buf == 2 ? SVHI : SVLO;
            cpa16(sb + off + r * STRB + ch * 16,
                  (const char*)base + (bi + (size_t)r * DD + ch * 8) * 2, 16);
        }
    }
    CP_COMMIT();

    float oacc[2][4][4];
    #pragma unroll
    for (int a = 0; a < 2; a++)
        #pragma unroll
        for (int nb = 0; nb < 4; nb++)
            #pragma unroll
            for (int j = 0; j < 4; j++) oacc[a][nb][j] = 0.f;
    float rs[2][2] = {{0.f, 0.f}, {0.f, 0.f}};

    const uint32_t aSel = (l & 16) ? 16u : 0u;
    const uint32_t bRow = (l & 7) + ((l & 16) ? 8 : 0);
    const uint32_t bSel = (l & 8) ? 16u : 0u;
    const uint32_t aRow = (l & 15);

    for (int kt = 0; kt < NKT; kt++) {
        const int c0t = kt * NT;
        CP_WAIT0();
        __syncthreads();        // K/V/Q tiles ready; prev GEMM2 done (P/V free)

        // ---- GEMM1: S = Q K^T (3-term bf16 split, full accuracy for score) ----
        float sacc[2][4][4];
        #pragma unroll
        for (int a = 0; a < 2; a++)
            #pragma unroll
            for (int nb = 0; nb < 4; nb++)
                #pragma unroll
                for (int j = 0; j < 4; j++) sacc[a][nb][j] = 0.f;

        #pragma unroll
        for (int ks = 0; ks < 4; ks++) {
            const uint32_t kb = ks * 32;
            uint32_t ahi[2][4], alo[2][4], bhi[2][4], blo[2][4];
            #pragma unroll
            for (int a = 0; a < 2; a++) {
                uint32_t ro = (mi * 32 + a * 16 + aRow) * STRB + kb + aSel;
                LDM4(ahi[a], sb + SQHI + ro);
                LDM4(alo[a], sb + SQLO + ro);
            }
            #pragma unroll
            for (int np = 0; np < 2; np++) {
                uint32_t ro = (ni * 32 + np * 16 + bRow) * STRB + kb + bSel;
                LDM4(bhi[np], sb + SKHI + ro);
                LDM4(blo[np], sb + SKLO + ro);
            }
            #pragma unroll
            for (int a = 0; a < 2; a++)
                #pragma unroll
                for (int np = 0; np < 2; np++) {
                    MMA(sacc[a][2*np],   ahi[a], bhi[np][0], bhi[np][1]);
                    MMA(sacc[a][2*np],   alo[a], bhi[np][0], bhi[np][1]);
                    MMA(sacc[a][2*np],   ahi[a], blo[np][0], blo[np][1]);
                    MMA(sacc[a][2*np+1], ahi[a], bhi[np][2], bhi[np][3]);
                    MMA(sacc[a][2*np+1], alo[a], bhi[np][2], bhi[np][3]);
                    MMA(sacc[a][2*np+1], ahi[a], blo[np][2], blo[np][3]);
                }
        }

        // ---- epilogue: p = exp(mask(S*scale)); P(fp16)->smem, p->score (unnormalized) ----
        #pragma unroll
        for (int a = 0; a < 2; a++) {
            const int R0  = mi * 32 + a * 16 + (l >> 2);
            const int r0g = q0 + R0, r1g = r0g + 8;
            #pragma unroll
            for (int nb = 0; nb < 4; nb++) {
                const int col = ni * 32 + nb * 8 + 2 * (l & 3);
                const int cg  = c0t + col;
                float t0 = sacc[a][nb][0] * SC, t1 = sacc[a][nb][1] * SC;
                float t2 = sacc[a][nb][2] * SC, t3 = sacc[a][nb][3] * SC;
                if (r0g >= durb || cg     >= durb) t0 = 0.f;
                if (r0g >= durb || cg + 1 >= durb) t1 = 0.f;
                if (r1g >= durb || cg     >= durb) t2 = 0.f;
                if (r1g >= durb || cg + 1 >= durb) t3 = 0.f;
                float p0 = ex2f(t0), p1 = ex2f(t1), p2 = ex2f(t2), p3 = ex2f(t3);
                if (cg >= LL) { p0 = 0.f; p1 = 0.f; p2 = 0.f; p3 = 0.f; }
                rs[a][0] += p0 + p1;
                rs[a][1] += p2 + p3;
                uint32_t o0 = (R0 * STR + col) * 2;
                uint32_t o1 = ((R0 + 8) * STR + col) * 2;
                *(uint32_t*)(s + SPHI + o0) = cvt2h(p1, p0);
                *(uint32_t*)(s + SPHI + o1) = cvt2h(p3, p2);
                if (cg < LL) {
                    if (r0g < LL) *(float2*)(Sb + (size_t)r0g * LL + cg) = make_float2(p0, p1);
                    if (r1g < LL) *(float2*)(Sb + (size_t)r1g * LL + cg) = make_float2(p2, p3);
                }
            }
        }
        __syncthreads();        // P ready; all warps past GEMM1 -> K buffers free

        // ---- prefetch K(kt+1) (overlaps GEMM2) ----
        if (kt + 1 < NKT) {
            const int c0n = c0t + NT;
            #pragma unroll
            for (int w = 0; w < 4; w++) {
                int c = tid + 256 * w;      // 0..1023
                int buf = c >> 9;           // 0:hi 1:lo
                int r = (c >> 3) & 63;
                int ch = c & 7;
                int rg = c0n + r;
                int rc = rg < LL ? rg : LL - 1;
                const __nv_bfloat16* src = (buf ? g_klo : g_khi) + bi + (size_t)rc * DD + ch * 8;
                cpa16(sb + (buf ? SKLO : SKHI) + r * STRB + ch * 16, src, rg < LL ? 16 : 0);
            }
        }

        // ---- GEMM2: out += P V (P fp16 single, V fp16 hi+lo: 2-term) ----
        #pragma unroll
        for (int ks = 0; ks < 4; ks++) {
            const uint32_t kb = ks * 32;
            uint32_t pa[2][4], bhi[2][4], blo[2][4];
            #pragma unroll
            for (int a = 0; a < 2; a++) {
                uint32_t ro = (mi * 32 + a * 16 + aRow) * STRB + kb + aSel;
                LDM4(pa[a], sb + SPHI + ro);
            }
            #pragma unroll
            for (int np = 0; np < 2; np++) {
                uint32_t ro = (ks * 16 + aRow) * STRB + (ni * 32 + np * 16) * 2 + aSel;
                LDM4T(bhi[np], sb + SVHI + ro);
                LDM4T(blo[np], sb + SVLO + ro);
            }
            #pragma unroll
            for (int a = 0; a < 2; a++)
                #pragma unroll
                for (int np = 0; np < 2; np++) {
                    MMAH(oacc[a][2*np],   pa[a], bhi[np][0], bhi[np][1]);
                    MMAH(oacc[a][2*np],   pa[a], blo[np][0], blo[np][1]);
                    MMAH(oacc[a][2*np+1], pa[a], bhi[np][2], bhi[np][3]);
                    MMAH(oacc[a][2*np+1], pa[a], blo[np][2], blo[np][3]);
                }
        }
        __syncthreads();        // all warps past GEMM2 -> V/P free

        // ---- prefetch V(kt+1), commit the K+V group ----
        if (kt + 1 < NKT) {
            const int c0n = c0t + NT;
            #pragma unroll
            for (int w = 0; w < 4; w++) {
                int c = tid + 256 * w;
                int buf = c >> 9;
                int r = (c >> 3) & 63;
                int ch = c & 7;
                int rg = c0n + r;
                int rc = rg < LL ? rg : LL - 1;
                const __half* src = (buf ? g_vlo : g_vhi) + bi + (size_t)rc * DD + ch * 8;
                cpa16(sb + (buf ? SVLO : SVHI) + r * STRB + ch * 16, src, rg < LL ? 16 : 0);
            }
            CP_COMMIT();
        }
    }

    // ---- rowsum reduce -> invl ----
    #pragma unroll
    for (int a = 0; a < 2; a++)
        #pragma unroll
        for (int h = 0; h < 2; h++) {
            float vsum = rs[a][h];
            vsum += __shfl_xor_sync(0xffffffffu, vsum, 1);
            vsum += __shfl_xor_sync(0xffffffffu, vsum, 2);
            if ((l & 3) == 0)
                atomicAdd((float*)(s + SSL) + (mi * 32 + a * 16 + (l >> 2) + 8 * h), vsum);
        }
    __syncthreads();
    if (tid < 128) {
        float inv = 1.f / ((float*)(s + SSL))[tid];
        ((float*)(s + SSINV))[tid] = inv;
        int rg = q0 + tid;
        if (rg < LL) g_invl[b * LL + rg] = inv;
    }
    __syncthreads();

    const float* sinv = (const float*)(s + SSINV);

    // ---- out = (P V) * invl ----
    #pragma unroll
    for (int a = 0; a < 2; a++) {
        const int R0 = mi * 32 + a * 16 + (l >> 2);
        const float inv0 = sinv[R0], inv1 = sinv[R0 + 8];
        const int r0g = q0 + R0, r1g = r0g + 8;
        #pragma unroll
        for (int nb = 0; nb < 4; nb++) {
            const int d0 = ni * 32 + nb * 8 + 2 * (l & 3);
            if (r0g < LL)
                *(float2*)(out + ((size_t)b * LL + r0g) * DD + d0) =
                    make_float2(oacc[a][nb][0] * inv0, oacc[a][nb][1] * inv0);
            if (r1g < LL)
                *(float2*)(out + ((size_t)b * LL + r1g) * DD + d0) =
                    make_float2(oacc[a][nb][2] * inv1, oacc[a][nb][3] * inv1);
        }
    }
}

// score[row] *= invl[row]  (225 float4 per row, coalesced)
__global__ __launch_bounds__(256)
void norm_score(float* __restrict__ score)
{
    const int row = blockIdx.x;
    const int t   = threadIdx.x;
    if (t >= 225) return;
    const float inv = g_invl[row];
    float4* p = (float4*)(score + (size_t)row * LL) + t;
    float4 sv = *p;
    sv.x *= inv; sv.y *= inv; sv.z *= inv; sv.w *= inv;
    *p = sv;
}

extern "C" void kernel_launch(void* const* d_in, const int* in_sizes, int n_in,
                              void* d_out, int out_size)
{
    const float* q   = (const float*)d_in[0];
    const float* k   = (const float*)d_in[1];
    const float* v   = (const float*)d_in[2];
    const int*   dur = (const int*)d_in[3];

    float* out   = (float*)d_out;
    float* score = out + (size_t)BB * LL * DD;

    const int N4 = NELEM / 4;
    precvt<<<(3 * N4 + 255) / 256, 256>>>(q, k, v);

    cudaFuncSetAttribute(attn_mma, cudaFuncAttributeMaxDynamicSharedMemorySize, SMEM_BYTES);
    dim3 grd(8, BB);
    attn_mma<<<grd, 256, SMEM_BYTES>>>(dur, out, score);

    norm_score<<<BB * LL, 256>>>(score);
}

// round 10
// speedup vs baseline: 2.1542x; 1.1877x over previous
#include <cuda_runtime.h>
#include <cuda_bf16.h>
#include <cuda_fp16.h>
#include <math.h>
#include <stdint.h>

#define BB 64
#define LL 900
#define DD 64
#define MT 128
#define NT 64
#define NKT 15
#define SC 0.180336893f   // 0.125 * log2(e)

#define STR  72           // 16-bit elems per smem row (144B)
#define STRB 144

// smem byte offsets
#define SQ    0           // Q fp16 single: 128 x 144B
#define SK    18432       // K fp16 single: 64 x 144B
#define SVHI  27648
#define SVLO  36864
#define SP    46080       // P fp16 single: 128 x 144B
#define SSL   64512
#define SSINV 65024
#define SMEM_BYTES 65536

#define NELEM (BB * LL * DD)

__device__ __half g_qh[NELEM];                    // fp16 single
__device__ __half g_kh[NELEM];                    // fp16 single
__device__ __half g_vhi[NELEM], g_vlo[NELEM];     // fp16 split for GEMM2
__device__ float g_invl[BB * LL];

static __device__ __forceinline__ uint32_t smem_u32(const void* p) {
    uint32_t a;
    asm("{ .reg .u64 t; cvta.to.shared.u64 t, %1; cvt.u32.u64 %0, t; }" : "=r"(a) : "l"(p));
    return a;
}
static __device__ __forceinline__ float ex2f(float x) {
    float r; asm("ex2.approx.ftz.f32 %0, %1;" : "=f"(r) : "f"(x)); return r;
}
// pack two f32 -> f16x2
static __device__ __forceinline__ uint32_t cvt2h(float hi, float lo) {
    uint32_t r; asm("cvt.rn.f16x2.f32 %0, %1, %2;" : "=r"(r) : "f"(hi), "f"(lo)); return r;
}
static __device__ __forceinline__ void cpa16(uint32_t dst, const void* src, int sz) {
    asm volatile("cp.async.cg.shared.global [%0], [%1], 16, %2;"
                 :: "r"(dst), "l"(src), "r"(sz) : "memory");
}
#define CP_COMMIT() asm volatile("cp.async.commit_group;" ::: "memory")
#define CP_WAIT0()  asm volatile("cp.async.wait_group 0;" ::: "memory")

#define LDM4(r, a) \
    asm volatile("ldmatrix.sync.aligned.m8n8.x4.shared.b16 {%0,%1,%2,%3}, [%4];" \
        : "=r"((r)[0]), "=r"((r)[1]), "=r"((r)[2]), "=r"((r)[3]) : "r"(a))
#define LDM4T(r, a) \
    asm volatile("ldmatrix.sync.aligned.m8n8.x4.trans.shared.b16 {%0,%1,%2,%3}, [%4];" \
        : "=r"((r)[0]), "=r"((r)[1]), "=r"((r)[2]), "=r"((r)[3]) : "r"(a))
#define MMAH(d, a, b0, b1) \
    asm volatile("mma.sync.aligned.m16n8k16.row.col.f32.f16.f16.f32 " \
        "{%0,%1,%2,%3}, {%4,%5,%6,%7}, {%8,%9}, {%0,%1,%2,%3};" \
        : "+f"((d)[0]), "+f"((d)[1]), "+f"((d)[2]), "+f"((d)[3]) \
        : "r"((a)[0]), "r"((a)[1]), "r"((a)[2]), "r"((a)[3]), "r"(b0), "r"(b1))

// ---------- precvt: q,k -> fp16 single;  v -> fp16 hi/lo ----------
__global__ __launch_bounds__(256)
void precvt(const float* __restrict__ q, const float* __restrict__ k,
            const float* __restrict__ v)
{
    const int N4 = NELEM / 4;
    int i = blockIdx.x * blockDim.x + threadIdx.x;
    if (i >= 3 * N4) return;
    int t  = i / N4;
    int i4 = i - t * N4;
    if (t < 2) {
        float4 val = ((const float4*)(t == 0 ? q : k))[i4];
        uint32_t a01 = cvt2h(val.y, val.x);
        uint32_t a23 = cvt2h(val.w, val.z);
        ((uint2*)(t == 0 ? g_qh : g_kh))[i4] = make_uint2(a01, a23);
    } else {
        float4 val = ((const float4*)v)[i4];
        __half h0 = __float2half(val.x), h1 = __float2half(val.y);
        __half h2 = __float2half(val.z), h3 = __float2half(val.w);
        __half l0 = __float2half(val.x - __half2float(h0));
        __half l1 = __float2half(val.y - __half2float(h1));
        __half l2 = __float2half(val.z - __half2float(h2));
        __half l3 = __float2half(val.w - __half2float(h3));
        __half2 hv0 = __halves2half2(h0, h1), hv1 = __halves2half2(h2, h3);
        __half2 lv0 = __halves2half2(l0, l1), lv1 = __halves2half2(l2, l3);
        ((uint2*)g_vhi)[i4] = make_uint2(*(uint32_t*)&hv0, *(uint32_t*)&hv1);
        ((uint2*)g_vlo)[i4] = make_uint2(*(uint32_t*)&lv0, *(uint32_t*)&lv1);
    }
}

// ---------- fused attention ----------
__global__ void __launch_bounds__(256, 2)
attn_mma(const int* __restrict__ dur, float* __restrict__ out, float* __restrict__ score)
{
    extern __shared__ char s[];
    const uint32_t sb = smem_u32(s);

    const int tid = threadIdx.x;
    const int l   = tid & 31;
    const int wid = tid >> 5;
    const int mi  = wid >> 1;
    const int ni  = wid & 1;
    const int b   = blockIdx.y;
    const int q0  = blockIdx.x * MT;
    const int durb = dur[b];
    const size_t bi = (size_t)b * LL * DD;

    float* Sb = score + (size_t)b * LL * LL;

    if (tid < 128) *(float*)(s + SSL + tid * 4) = 0.f;

    // ---- prologue: cp.async Q + K0 + V0(hi/lo) ----
    #pragma unroll
    for (int w = 0; w < 4; w++) {      // Q: 1024 16B-chunks
        int c = tid + 256 * w;
        int r = c >> 3, ch = c & 7;
        int rg = q0 + r;
        int rc = rg < LL ? rg : LL - 1;
        cpa16(sb + SQ + r * STRB + ch * 16,
              g_qh + bi + (size_t)rc * DD + ch * 8, rg < LL ? 16 : 0);
    }
    #pragma unroll
    for (int w = 0; w < 2; w++) {      // K0: 512 chunks
        int c = tid + 256 * w;
        int r = c >> 3, ch = c & 7;
        cpa16(sb + SK + r * STRB + ch * 16, g_kh + bi + (size_t)r * DD + ch * 8, 16);
    }
    #pragma unroll
    for (int w = 0; w < 4; w++) {      // V0 hi/lo: 1024 chunks
        int c = tid + 256 * w;
        int buf = c >> 9;
        int r = (c >> 3) & 63, ch = c & 7;
        const __half* base = buf ? g_vlo : g_vhi;
        cpa16(sb + (buf ? SVLO : SVHI) + r * STRB + ch * 16,
              base + bi + (size_t)r * DD + ch * 8, 16);
    }
    CP_COMMIT();

    float oacc[2][4][4];
    #pragma unroll
    for (int a = 0; a < 2; a++)
        #pragma unroll
        for (int nb = 0; nb < 4; nb++)
            #pragma unroll
            for (int j = 0; j < 4; j++) oacc[a][nb][j] = 0.f;
    float rs[2][2] = {{0.f, 0.f}, {0.f, 0.f}};

    const uint32_t aSel = (l & 16) ? 16u : 0u;
    const uint32_t bRow = (l & 7) + ((l & 16) ? 8 : 0);
    const uint32_t bSel = (l & 8) ? 16u : 0u;
    const uint32_t aRow = (l & 15);

    for (int kt = 0; kt < NKT; kt++) {
        const int c0t = kt * NT;
        CP_WAIT0();
        __syncthreads();        // tiles ready; prev GEMM2 done

        // ---- GEMM1: S = Q K^T (single fp16) ----
        float sacc[2][4][4];
        #pragma unroll
        for (int a = 0; a < 2; a++)
            #pragma unroll
            for (int nb = 0; nb < 4; nb++)
                #pragma unroll
                for (int j = 0; j < 4; j++) sacc[a][nb][j] = 0.f;

        #pragma unroll
        for (int ks = 0; ks < 4; ks++) {
            const uint32_t kb = ks * 32;
            uint32_t qa[2][4], kf[2][4];
            #pragma unroll
            for (int a = 0; a < 2; a++) {
                uint32_t ro = (mi * 32 + a * 16 + aRow) * STRB + kb + aSel;
                LDM4(qa[a], sb + SQ + ro);
            }
            #pragma unroll
            for (int np = 0; np < 2; np++) {
                uint32_t ro = (ni * 32 + np * 16 + bRow) * STRB + kb + bSel;
                LDM4(kf[np], sb + SK + ro);
            }
            #pragma unroll
            for (int a = 0; a < 2; a++)
                #pragma unroll
                for (int np = 0; np < 2; np++) {
                    MMAH(sacc[a][2*np],   qa[a], kf[np][0], kf[np][1]);
                    MMAH(sacc[a][2*np+1], qa[a], kf[np][2], kf[np][3]);
                }
        }

        // ---- epilogue: p = exp(mask(S*scale)); P(fp16)->smem, p->score (unnormalized) ----
        #pragma unroll
        for (int a = 0; a < 2; a++) {
            const int R0  = mi * 32 + a * 16 + (l >> 2);
            const int r0g = q0 + R0, r1g = r0g + 8;
            #pragma unroll
            for (int nb = 0; nb < 4; nb++) {
                const int col = ni * 32 + nb * 8 + 2 * (l & 3);
                const int cg  = c0t + col;
                float t0 = sacc[a][nb][0] * SC, t1 = sacc[a][nb][1] * SC;
                float t2 = sacc[a][nb][2] * SC, t3 = sacc[a][nb][3] * SC;
                if (r0g >= durb || cg     >= durb) t0 = 0.f;
                if (r0g >= durb || cg + 1 >= durb) t1 = 0.f;
                if (r1g >= durb || cg     >= durb) t2 = 0.f;
                if (r1g >= durb || cg + 1 >= durb) t3 = 0.f;
                float p0 = ex2f(t0), p1 = ex2f(t1), p2 = ex2f(t2), p3 = ex2f(t3);
                if (cg >= LL) { p0 = 0.f; p1 = 0.f; p2 = 0.f; p3 = 0.f; }
                rs[a][0] += p0 + p1;
                rs[a][1] += p2 + p3;
                uint32_t o0 = (R0 * STR + col) * 2;
                uint32_t o1 = ((R0 + 8) * STR + col) * 2;
                *(uint32_t*)(s + SP + o0) = cvt2h(p1, p0);
                *(uint32_t*)(s + SP + o1) = cvt2h(p3, p2);
                if (cg < LL) {
                    if (r0g < LL) *(float2*)(Sb + (size_t)r0g * LL + cg) = make_float2(p0, p1);
                    if (r1g < LL) *(float2*)(Sb + (size_t)r1g * LL + cg) = make_float2(p2, p3);
                }
            }
        }
        __syncthreads();        // P ready; K buffer free

        // ---- prefetch K(kt+1) (overlaps GEMM2) ----
        if (kt + 1 < NKT) {
            const int c0n = c0t + NT;
            #pragma unroll
            for (int w = 0; w < 2; w++) {
                int c = tid + 256 * w;
                int r = c >> 3, ch = c & 7;
                int rg = c0n + r;
                int rc = rg < LL ? rg : LL - 1;
                cpa16(sb + SK + r * STRB + ch * 16,
                      g_kh + bi + (size_t)rc * DD + ch * 8, rg < LL ? 16 : 0);
            }
        }

        // ---- GEMM2: out += P V (P fp16 single, V fp16 hi+lo: 2-term) ----
        #pragma unroll
        for (int ks = 0; ks < 4; ks++) {
            const uint32_t kb = ks * 32;
            uint32_t pa[2][4], bhi[2][4], blo[2][4];
            #pragma unroll
            for (int a = 0; a < 2; a++) {
                uint32_t ro = (mi * 32 + a * 16 + aRow) * STRB + kb + aSel;
                LDM4(pa[a], sb + SP + ro);
            }
            #pragma unroll
            for (int np = 0; np < 2; np++) {
                uint32_t ro = (ks * 16 + aRow) * STRB + (ni * 32 + np * 16) * 2 + aSel;
                LDM4T(bhi[np], sb + SVHI + ro);
                LDM4T(blo[np], sb + SVLO + ro);
            }
            #pragma unroll
            for (int a = 0; a < 2; a++)
                #pragma unroll
                for (int np = 0; np < 2; np++) {
                    MMAH(oacc[a][2*np],   pa[a], bhi[np][0], bhi[np][1]);
                    MMAH(oacc[a][2*np],   pa[a], blo[np][0], blo[np][1]);
                    MMAH(oacc[a][2*np+1], pa[a], bhi[np][2], bhi[np][3]);
                    MMAH(oacc[a][2*np+1], pa[a], blo[np][2], blo[np][3]);
                }
        }
        __syncthreads();        // V/P free

        // ---- prefetch V(kt+1), commit the K+V group ----
        if (kt + 1 < NKT) {
            const int c0n = c0t + NT;
            #pragma unroll
            for (int w = 0; w < 4; w++) {
                int c = tid + 256 * w;
                int buf = c >> 9;
                int r = (c >> 3) & 63, ch = c & 7;
                int rg = c0n + r;
                int rc = rg < LL ? rg : LL - 1;
                const __half* src = (buf ? g_vlo : g_vhi) + bi + (size_t)rc * DD + ch * 8;
                cpa16(sb + (buf ? SVLO : SVHI) + r * STRB + ch * 16, src, rg < LL ? 16 : 0);
            }
            CP_COMMIT();
        }
    }

    // ---- rowsum reduce -> invl ----
    #pragma unroll
    for (int a = 0; a < 2; a++)
        #pragma unroll
        for (int h = 0; h < 2; h++) {
            float vsum = rs[a][h];
            vsum += __shfl_xor_sync(0xffffffffu, vsum, 1);
            vsum += __shfl_xor_sync(0xffffffffu, vsum, 2);
            if ((l & 3) == 0)
                atomicAdd((float*)(s + SSL) + (mi * 32 + a * 16 + (l >> 2) + 8 * h), vsum);
        }
    __syncthreads();
    if (tid < 128) {
        float inv = 1.f / ((float*)(s + SSL))[tid];
        ((float*)(s + SSINV))[tid] = inv;
        int rg = q0 + tid;
        if (rg < LL) g_invl[b * LL + rg] = inv;
    }
    __syncthreads();

    const float* sinv = (const float*)(s + SSINV);

    // ---- out = (P V) * invl ----
    #pragma unroll
    for (int a = 0; a < 2; a++) {
        const int R0 = mi * 32 + a * 16 + (l >> 2);
        const float inv0 = sinv[R0], inv1 = sinv[R0 + 8];
        const int r0g = q0 + R0, r1g = r0g + 8;
        #pragma unroll
        for (int nb = 0; nb < 4; nb++) {
            const int d0 = ni * 32 + nb * 8 + 2 * (l & 3);
            if (r0g < LL)
                *(float2*)(out + ((size_t)b * LL + r0g) * DD + d0) =
                    make_float2(oacc[a][nb][0] * inv0, oacc[a][nb][1] * inv0);
            if (r1g < LL)
                *(float2*)(out + ((size_t)b * LL + r1g) * DD + d0) =
                    make_float2(oacc[a][nb][2] * inv1, oacc[a][nb][3] * inv1);
        }
    }
}

// score *= invl[row], flat thread-per-float4 (full thread utilization)
__global__ __launch_bounds__(256)
void norm_score(float* __restrict__ score)
{
    const int T4 = BB * LL * LL / 4;           // 12,960,000
    int idx = blockIdx.x * blockDim.x + threadIdx.x;
    if (idx >= T4) return;
    int row = idx / (LL / 4);                  // 225 float4s per row
    const float inv = g_invl[row];
    float4 sv = ((const float4*)score)[idx];
    sv.x *= inv; sv.y *= inv; sv.z *= inv; sv.w *= inv;
    ((float4*)score)[idx] = sv;
}

extern "C" void kernel_launch(void* const* d_in, const int* in_sizes, int n_in,
                              void* d_out, int out_size)
{
    const float* q   = (const float*)d_in[0];
    const float* k   = (const float*)d_in[1];
    const float* v   = (const float*)d_in[2];
    const int*   dur = (const int*)d_in[3];

    float* out   = (float*)d_out;
    float* score = out + (size_t)BB * LL * DD;

    const int N4 = NELEM / 4;
    precvt<<<(3 * N4 + 255) / 256, 256>>>(q, k, v);

    cudaFuncSetAttribute(attn_mma, cudaFuncAttributeMaxDynamicSharedMemorySize, SMEM_BYTES);
    dim3 grd(8, BB);
    attn_mma<<<grd, 256, SMEM_BYTES>>>(dur, out, score);

    const int T4 = BB * LL * LL / 4;
    norm_score<<<(T4 + 255) / 256, 256>>>(score);
}